// round 1
// baseline (speedup 1.0000x reference)
#include <cuda_runtime.h>
#include <cstdint>

#define NF 5
#define NK 6
#define NT 12
#define NR 16
#define NM 3600
#define NS 400
#define NB 128
#define NSPLIT 24
#define MPW 150            // NM / NSPLIT

#define TWO_PI_D    6.283185307179586
#define INV_TWO_PI_D 0.15915494309189535
#define PI_F        3.14159265358979f
#define THETA_HI    0.3490658503988659f   // 20*pi/180

// ---------------- scratch (device globals; no allocation) ----------------
__device__ float4 g_C1[NF * NM * 3];            // [f][m][k0..5] as 3 x float4 (complex pairs)
__device__ float4 g_C2[NF * NM * 8];            // [f][m][r0..15] as 8 x float4
__device__ float4 g_meta4[NM];                  // padded meta positions
__device__ float2 g_A2p[NSPLIT * NF * NK * NS]; // partial A2 per m-split
__device__ float2 g_Gp [NSPLIT * NF * NS * NR]; // partial G per m-split
__device__ float2 g_A2[NF * NK * NS];           // A2[f][k][s]
__device__ float2 g_G [NF * NS * NR];           // G[f][s][r]

// amp * exp(-i * kd * d), amp = 1e-3 / d^2.  kd*d computed in fp64, reduced to
// [-pi,pi], then fast intrinsic sincos (accurate in that range).
__device__ __forceinline__ float2 cexp_amp(double kd, float d) {
    float amp = __fdividef(1e-3f, d * d);
    double ang = kd * (double)d;
    double q = rint(ang * INV_TWO_PI_D);
    float ar = (float)(ang - q * TWO_PI_D);
    float sn, cs;
    __sincosf(ar, &sn, &cs);
    return make_float2(amp * cs, -amp * sn);
}

__device__ __forceinline__ void cmac(float& ar, float& ai, float cr, float ci, float2 h) {
    ar = fmaf(cr, h.x, ar); ar = fmaf(-ci, h.y, ar);
    ai = fmaf(cr, h.y, ai); ai = fmaf(ci, h.x, ai);
}

// ---------------- kernel 1: C1, C2, meta4 ----------------
// thread <-> (f, m); grid covers NF*NM
__global__ void k_setup(const float* __restrict__ w,   const float* __restrict__ theta_in,
                        const float* __restrict__ fv,  const float* __restrict__ txp,
                        const float* __restrict__ rxp, const float* __restrict__ metap) {
    __shared__ float2 spri[NF * NK * NT];
    __shared__ float  stx[NT * 3];
    __shared__ float  srx[NR * 3];
    __shared__ float  sf[NF];
    int tid = threadIdx.x;
    if (tid < NT * 3) stx[tid] = txp[tid];
    if (tid >= 64 && tid < 64 + NR * 3) srx[tid - 64] = rxp[tid - 64];
    if (tid >= 128 && tid < 128 + NF) sf[tid - 128] = fv[tid - 128];
    for (int i = tid; i < NF * NK * NT; i += blockDim.x) {
        float s, c; sincosf(w[i], &s, &c);
        spri[i] = make_float2(c, s);                    // exp(i w)
    }
    __syncthreads();

    int g = blockIdx.x * blockDim.x + tid;
    if (g >= NF * NM) return;
    int fi = g / NM;
    int m  = g - fi * NM;

    float th = theta_in[m];
    th = fminf(fmaxf(th, -PI_F), THETA_HI);
    float ps, pc; __sincosf(th, &ps, &pc);              // phase = pc + i ps

    float mx = metap[3 * m + 0], my = metap[3 * m + 1], mz = metap[3 * m + 2];
    if (fi == 0) g_meta4[m] = make_float4(mx, my, mz, 0.f);

    double kd = TWO_PI_D * (double)sf[fi] / 3.0e8;

    float2 h1[NT];
    #pragma unroll
    for (int t = 0; t < NT; t++) {
        float dx = stx[3 * t + 0] - mx, dy = stx[3 * t + 1] - my, dz = stx[3 * t + 2] - mz;
        float d = sqrtf(dx * dx + dy * dy + dz * dz);
        h1[t] = cexp_amp(kd, d);
    }
    float2* C1 = (float2*)g_C1;
    size_t base = (size_t)fi * NM + m;
    #pragma unroll
    for (int k = 0; k < NK; k++) {
        float ar = 0.f, ai = 0.f;
        #pragma unroll
        for (int t = 0; t < NT; t++) {
            float2 p = spri[(fi * NK + k) * NT + t];
            cmac(ar, ai, p.x, p.y, h1[t]);
        }
        // multiply by meta phase
        C1[base * NK + k] = make_float2(ar * pc - ai * ps, ar * ps + ai * pc);
    }
    float2* C2 = (float2*)g_C2;
    #pragma unroll
    for (int r = 0; r < NR; r++) {
        float dx = srx[3 * r + 0] - mx, dy = srx[3 * r + 1] - my, dz = srx[3 * r + 2] - mz;
        float d = sqrtf(dx * dx + dy * dy + dz * dz);
        float2 h = cexp_amp(kd, d);
        C2[base * NR + r] = make_float2(pc * h.x - ps * h.y, pc * h.y + ps * h.x);
    }
}

// ---------------- kernel 2: fused A2 + G partial sums ----------------
// grid (13, NF, 3), block 256 = 8 warps. lane <-> scene within s-group,
// warp <-> m-split. All C1/C2/meta loads are warp-uniform (broadcast).
__global__ void k_main(const float* __restrict__ scenep, const float* __restrict__ fv) {
    int warp = threadIdx.x >> 5;
    int lane = threadIdx.x & 31;
    int sg = blockIdx.x;                 // 0..12
    int f  = blockIdx.y;                 // 0..4
    int msplit = blockIdx.z * 8 + warp;  // 0..23
    int s = sg * 32 + lane;
    bool valid = (s < NS);
    int sc = valid ? s : 0;
    float sx = scenep[3 * sc + 0], sy = scenep[3 * sc + 1], sz = scenep[3 * sc + 2];
    double kd = TWO_PI_D * (double)__ldg(&fv[f]) / 3.0e8;

    float aA[2 * NK];
    float aG[2 * NR];
    #pragma unroll
    for (int i = 0; i < 2 * NK; i++) aA[i] = 0.f;
    #pragma unroll
    for (int i = 0; i < 2 * NR; i++) aG[i] = 0.f;

    const float4* c1b = g_C1 + (size_t)f * NM * 3;
    const float4* c2b = g_C2 + (size_t)f * NM * 8;
    int m0 = msplit * MPW;

    #pragma unroll 2
    for (int m = m0; m < m0 + MPW; ++m) {
        float4 mp = __ldg(&g_meta4[m]);
        float dx = mp.x - sx, dy = mp.y - sy, dz = mp.z - sz;
        float d = sqrtf(fmaf(dx, dx, fmaf(dy, dy, dz * dz)));
        float2 h = cexp_amp(kd, d);                    // H2[f][m][s]

        float4 u0 = __ldg(c1b + (size_t)m * 3 + 0);
        float4 u1 = __ldg(c1b + (size_t)m * 3 + 1);
        float4 u2 = __ldg(c1b + (size_t)m * 3 + 2);
        cmac(aA[0],  aA[1],  u0.x, u0.y, h);
        cmac(aA[2],  aA[3],  u0.z, u0.w, h);
        cmac(aA[4],  aA[5],  u1.x, u1.y, h);
        cmac(aA[6],  aA[7],  u1.z, u1.w, h);
        cmac(aA[8],  aA[9],  u2.x, u2.y, h);
        cmac(aA[10], aA[11], u2.z, u2.w, h);

        #pragma unroll
        for (int j = 0; j < 8; ++j) {
            float4 v = __ldg(c2b + (size_t)m * 8 + j);
            int r2 = 4 * j;
            cmac(aG[r2 + 0], aG[r2 + 1], v.x, v.y, h);
            cmac(aG[r2 + 2], aG[r2 + 3], v.z, v.w, h);
        }
    }

    if (valid) {
        float2* A2p = g_A2p + (size_t)msplit * (NF * NK * NS);
        #pragma unroll
        for (int k = 0; k < NK; k++)
            A2p[(f * NK + k) * NS + s] = make_float2(aA[2 * k], aA[2 * k + 1]);
        float2* Gp = g_Gp + (size_t)msplit * (NF * NS * NR);
        #pragma unroll
        for (int r = 0; r < NR; r++)
            Gp[((size_t)f * NS + s) * NR + r] = make_float2(aG[2 * r], aG[2 * r + 1]);
    }
}

// ---------------- kernel 3: reduce partials ----------------
__global__ void k_reduce() {
    int i = blockIdx.x * blockDim.x + threadIdx.x;
    if (i < NF * NK * NS) {
        float2 acc = make_float2(0.f, 0.f);
        #pragma unroll
        for (int j = 0; j < NSPLIT; j++) {
            float2 p = g_A2p[(size_t)j * (NF * NK * NS) + i];
            acc.x += p.x; acc.y += p.y;
        }
        g_A2[i] = acc;
    } else if (i < NF * NK * NS + NF * NS * NR) {
        int gi = i - NF * NK * NS;
        float2 acc = make_float2(0.f, 0.f);
        #pragma unroll
        for (int j = 0; j < NSPLIT; j++) {
            float2 p = g_Gp[(size_t)j * (NF * NS * NR) + gi];
            acc.x += p.x; acc.y += p.y;
        }
        g_G[gi] = acc;
    }
}

// ---------------- kernel 4: outputs ----------------
// block <-> (r, f). V[k][s] = A2[f][k][s] * G[f][s][r] in shared.
// s_A = replicated re/im of V; mic = V @ T, replicated.
__global__ void k_out(const float* __restrict__ T, float* __restrict__ out) {
    __shared__ float2 sV[NK][NS];
    int bx = blockIdx.x;
    int r = bx / NF;
    int f = bx - r * NF;
    int tid = threadIdx.x;  // 256

    for (int s = tid; s < NS; s += blockDim.x) {
        float2 g = g_G[((size_t)f * NS + s) * NR + r];
        #pragma unroll
        for (int k = 0; k < NK; k++) {
            float2 a = g_A2[(f * NK + k) * NS + s];
            sV[k][s] = make_float2(a.x * g.x - a.y * g.y, a.x * g.y + a.y * g.x);
        }
    }
    __syncthreads();

    int rowbase = r * (NF * 72) + f * 72;

    // s_A: rows 0..5759 real, 5760..11519 imag
    #pragma unroll
    for (int k = 0; k < NK; k++) {
        for (int s = tid; s < NS; s += blockDim.x) {
            float2 v = sV[k][s];
            #pragma unroll
            for (int rep = 0; rep < 12; rep++) {
                int row = rowbase + rep * NK + k;
                out[(size_t)row * NS + s] = v.x;
                out[(size_t)(5760 + row) * NS + s] = v.y;
            }
        }
    }

    // mic: 256 threads = 2 halves x 128 columns; each half does 3 k's
    int b  = tid & (NB - 1);
    int kh = tid >> 7;  // 0 or 1
    float mre[3] = {0.f, 0.f, 0.f}, mim[3] = {0.f, 0.f, 0.f};
    for (int s = 0; s < NS; s++) {
        float t = __ldg(&T[s * NB + b]);
        #pragma unroll
        for (int j = 0; j < 3; j++) {
            float2 v = sV[kh * 3 + j][s];
            mre[j] = fmaf(v.x, t, mre[j]);
            mim[j] = fmaf(v.y, t, mim[j]);
        }
    }
    const size_t MICBASE = (size_t)11520 * NS;
    #pragma unroll
    for (int j = 0; j < 3; j++) {
        int k = kh * 3 + j;
        #pragma unroll
        for (int rep = 0; rep < 12; rep++) {
            int row = rowbase + rep * NK + k;
            out[MICBASE + (size_t)row * NB + b] = mre[j];
            out[MICBASE + (size_t)(5760 + row) * NB + b] = mim[j];
        }
    }
}

// ---------------- launcher ----------------
extern "C" void kernel_launch(void* const* d_in, const int* in_sizes, int n_in,
                              void* d_out, int out_size) {
    const float* T   = (const float*)d_in[0];  // [400,128]
    const float* w   = (const float*)d_in[1];  // [5,6,12]
    const float* th  = (const float*)d_in[2];  // [3600,1]
    const float* fv  = (const float*)d_in[3];  // [5]
    const float* txp = (const float*)d_in[4];  // [12,3]
    const float* rxp = (const float*)d_in[5];  // [16,3]
    const float* mp  = (const float*)d_in[6];  // [3600,3]
    const float* sp  = (const float*)d_in[7];  // [400,3]
    float* out = (float*)d_out;

    k_setup<<<(NF * NM + 255) / 256, 256>>>(w, th, fv, txp, rxp, mp);
    k_main<<<dim3(13, NF, 3), 256>>>(sp, fv);
    k_reduce<<<(NF * NK * NS + NF * NS * NR + 255) / 256, 256>>>();
    k_out<<<NR * NF, 256>>>(T, out);
}

// round 2
// speedup vs baseline: 1.1710x; 1.1710x over previous
#include <cuda_runtime.h>
#include <cstdint>

#define NF 5
#define NK 6
#define NT 12
#define NR 16
#define NM 3600
#define NS 400
#define NB 128
#define NSPLIT 48
#define MPW 75             // NM / NSPLIT
#define NROW 5760          // Rx*F*72
#define NRFK 480           // Rx*F*6
#define MICCH 4            // s-chunks for mic partials

#define TWO_PI_D     6.283185307179586
#define INV2PI_F     0.15915494309189535f
#define PI2_HI_F     6.2831854820251465f
#define PI2_LO_F    -1.7484555e-7f
#define PI_F         3.14159265358979f
#define THETA_HI     0.3490658503988659f   // 20*pi/180

// ---------------- scratch (device globals; no allocation) ----------------
__device__ float4 g_C1[NF * NM * 3];            // [f][m][k0..5] complex pairs
__device__ float4 g_C2[NF * NM * 8];            // [f][m][r0..15] complex pairs
__device__ float4 g_meta4[NM];                  // padded meta positions
__device__ float2 g_A2p[NSPLIT * NF * NK * NS]; // partial A2 per m-split
__device__ float2 g_Gp [NSPLIT * NF * NR * NS]; // partial G per m-split [f][r][s]
__device__ float2 g_A2[NF * NK * NS];           // A2[f][k][s]
__device__ float2 g_G [NF * NR * NS];           // G[f][r][s]
__device__ float2 g_V [NR * NF * NK * NS];      // V[r][f][k][s]
__device__ float2 g_micp[MICCH * NRFK * NB];    // mic partials per s-chunk

// ---- fp32 two-product + Cody-Waite angle, then fast sincos --------------
// h = amp * exp(-i * ang), amp = 1e-3/d^2, ang = (kd_hi+kd_lo)*d reduced mod 2pi
__device__ __forceinline__ float2 cexp_amp_f(float kd_hi, float kd_lo, float d) {
    float amp = __fdividef(1e-3f, d * d);
    float p = kd_hi * d;
    float e = fmaf(kd_hi, d, -p);          // exact low part of product
    e = fmaf(kd_lo, d, e);
    float n = rintf(p * INV2PI_F);
    float r1 = fmaf(-n, PI2_HI_F, p);      // exact-ish: fma rounds once
    r1 = fmaf(-n, PI2_LO_F, r1);
    r1 += e;
    float sn, cs;
    __sincosf(r1, &sn, &cs);
    return make_float2(amp * cs, -amp * sn);
}

__device__ __forceinline__ float2 cexp_amp_d(double kd, float d) {
    float amp = __fdividef(1e-3f, d * d);
    double ang = kd * (double)d;
    double q = rint(ang * (double)INV2PI_F);
    float ar = (float)(ang - q * TWO_PI_D);
    float sn, cs;
    __sincosf(ar, &sn, &cs);
    return make_float2(amp * cs, -amp * sn);
}

__device__ __forceinline__ void cmac(float& ar, float& ai, float cr, float ci, float2 h) {
    ar = fmaf(cr, h.x, ar); ar = fmaf(-ci, h.y, ar);
    ai = fmaf(cr, h.y, ai); ai = fmaf(ci, h.x, ai);
}

// ---------------- kernel 1: C1, C2, meta4 ----------------
__global__ void k_setup(const float* __restrict__ w,   const float* __restrict__ theta_in,
                        const float* __restrict__ fv,  const float* __restrict__ txp,
                        const float* __restrict__ rxp, const float* __restrict__ metap) {
    __shared__ float2 spri[NF * NK * NT];
    __shared__ float  stx[NT * 3];
    __shared__ float  srx[NR * 3];
    __shared__ float  sf[NF];
    int tid = threadIdx.x;
    if (tid < NT * 3) stx[tid] = txp[tid];
    if (tid >= 64 && tid < 64 + NR * 3) srx[tid - 64] = rxp[tid - 64];
    if (tid >= 128 && tid < 128 + NF) sf[tid - 128] = fv[tid - 128];
    for (int i = tid; i < NF * NK * NT; i += blockDim.x) {
        float s, c; sincosf(w[i], &s, &c);
        spri[i] = make_float2(c, s);                    // exp(i w)
    }
    __syncthreads();

    int g = blockIdx.x * blockDim.x + tid;
    if (g >= NF * NM) return;
    int fi = g / NM;
    int m  = g - fi * NM;

    float th = theta_in[m];
    th = fminf(fmaxf(th, -PI_F), THETA_HI);
    float ps, pc; __sincosf(th, &ps, &pc);              // phase = pc + i ps

    float mx = metap[3 * m + 0], my = metap[3 * m + 1], mz = metap[3 * m + 2];
    if (fi == 0) g_meta4[m] = make_float4(mx, my, mz, 0.f);

    double kd = TWO_PI_D * (double)sf[fi] / 3.0e8;

    float2 h1[NT];
    #pragma unroll
    for (int t = 0; t < NT; t++) {
        float dx = stx[3 * t + 0] - mx, dy = stx[3 * t + 1] - my, dz = stx[3 * t + 2] - mz;
        float d = sqrtf(dx * dx + dy * dy + dz * dz);
        h1[t] = cexp_amp_d(kd, d);
    }
    float2* C1 = (float2*)g_C1;
    size_t base = (size_t)fi * NM + m;
    #pragma unroll
    for (int k = 0; k < NK; k++) {
        float ar = 0.f, ai = 0.f;
        #pragma unroll
        for (int t = 0; t < NT; t++) {
            float2 p = spri[(fi * NK + k) * NT + t];
            cmac(ar, ai, p.x, p.y, h1[t]);
        }
        C1[base * NK + k] = make_float2(ar * pc - ai * ps, ar * ps + ai * pc);
    }
    float2* C2 = (float2*)g_C2;
    #pragma unroll
    for (int r = 0; r < NR; r++) {
        float dx = srx[3 * r + 0] - mx, dy = srx[3 * r + 1] - my, dz = srx[3 * r + 2] - mz;
        float d = sqrtf(dx * dx + dy * dy + dz * dz);
        float2 h = cexp_amp_d(kd, d);
        C2[base * NR + r] = make_float2(pc * h.x - ps * h.y, pc * h.y + ps * h.x);
    }
}

// ---------------- kernel 2: fused A2 + G partial sums ----------------
// grid (13, NF, 6), block 256 = 8 warps. lane <-> scene, warp <-> m-split.
__global__ void k_main(const float* __restrict__ scenep, const float* __restrict__ fv) {
    int warp = threadIdx.x >> 5;
    int lane = threadIdx.x & 31;
    int sg = blockIdx.x;                 // 0..12
    int f  = blockIdx.y;                 // 0..4
    int msplit = blockIdx.z * 8 + warp;  // 0..47
    int s = sg * 32 + lane;
    bool valid = (s < NS);
    int sc = valid ? s : 0;
    float sx = scenep[3 * sc + 0], sy = scenep[3 * sc + 1], sz = scenep[3 * sc + 2];

    double kdd = TWO_PI_D * (double)__ldg(&fv[f]) / 3.0e8;
    float kd_hi = (float)kdd;
    float kd_lo = (float)(kdd - (double)kd_hi);

    float aA[2 * NK];
    float aG[2 * NR];
    #pragma unroll
    for (int i = 0; i < 2 * NK; i++) aA[i] = 0.f;
    #pragma unroll
    for (int i = 0; i < 2 * NR; i++) aG[i] = 0.f;

    const float4* c1b = g_C1 + (size_t)f * NM * 3;
    const float4* c2b = g_C2 + (size_t)f * NM * 8;
    int m0 = msplit * MPW;

    #pragma unroll 3
    for (int m = m0; m < m0 + MPW; ++m) {
        float4 mp = __ldg(&g_meta4[m]);
        float dx = mp.x - sx, dy = mp.y - sy, dz = mp.z - sz;
        float d = sqrtf(fmaf(dx, dx, fmaf(dy, dy, dz * dz)));
        float2 h = cexp_amp_f(kd_hi, kd_lo, d);        // H2[f][m][s]

        float4 u0 = __ldg(c1b + (size_t)m * 3 + 0);
        float4 u1 = __ldg(c1b + (size_t)m * 3 + 1);
        float4 u2 = __ldg(c1b + (size_t)m * 3 + 2);
        cmac(aA[0],  aA[1],  u0.x, u0.y, h);
        cmac(aA[2],  aA[3],  u0.z, u0.w, h);
        cmac(aA[4],  aA[5],  u1.x, u1.y, h);
        cmac(aA[6],  aA[7],  u1.z, u1.w, h);
        cmac(aA[8],  aA[9],  u2.x, u2.y, h);
        cmac(aA[10], aA[11], u2.z, u2.w, h);

        #pragma unroll
        for (int j = 0; j < 8; ++j) {
            float4 v = __ldg(c2b + (size_t)m * 8 + j);
            int r2 = 4 * j;
            cmac(aG[r2 + 0], aG[r2 + 1], v.x, v.y, h);
            cmac(aG[r2 + 2], aG[r2 + 3], v.z, v.w, h);
        }
    }

    if (valid) {
        float2* A2p = g_A2p + (size_t)msplit * (NF * NK * NS);
        #pragma unroll
        for (int k = 0; k < NK; k++)
            A2p[(f * NK + k) * NS + s] = make_float2(aA[2 * k], aA[2 * k + 1]);
        float2* Gp = g_Gp + (size_t)msplit * (NF * NR * NS);
        #pragma unroll
        for (int r = 0; r < NR; r++)
            Gp[(f * NR + r) * NS + s] = make_float2(aG[2 * r], aG[2 * r + 1]);
    }
}

// ---------------- kernel 3: reduce partials ----------------
__global__ void k_reduce() {
    int i = blockIdx.x * blockDim.x + threadIdx.x;
    if (i < NF * NK * NS) {
        float2 acc = make_float2(0.f, 0.f);
        #pragma unroll
        for (int j = 0; j < NSPLIT; j++) {
            float2 p = g_A2p[(size_t)j * (NF * NK * NS) + i];
            acc.x += p.x; acc.y += p.y;
        }
        g_A2[i] = acc;
    } else if (i < NF * NK * NS + NF * NR * NS) {
        int gi = i - NF * NK * NS;
        float2 acc = make_float2(0.f, 0.f);
        #pragma unroll
        for (int j = 0; j < NSPLIT; j++) {
            float2 p = g_Gp[(size_t)j * (NF * NR * NS) + gi];
            acc.x += p.x; acc.y += p.y;
        }
        g_G[gi] = acc;
    }
}

// ---------------- kernel 4: V[r][f][k][s] = A2[f][k][s] * G[f][r][s] ----
__global__ void k_V() {
    int id = blockIdx.x * blockDim.x + threadIdx.x;   // over NR*NF*NK*NS
    if (id >= NR * NF * NK * NS) return;
    int s = id % NS;
    int t = id / NS;          // (r*NF+f)*NK+k
    int k = t % NK;
    int t2 = t / NK;          // r*NF+f
    int f = t2 % NF;
    int r = t2 / NF;
    float2 a = g_A2[(f * NK + k) * NS + s];
    float2 g = g_G[(f * NR + r) * NS + s];
    g_V[id] = make_float2(a.x * g.x - a.y * g.y, a.x * g.y + a.y * g.x);
}

// ---------------- kernel 5: replicate s_A ----------------
// id over NROW*NS; row = r*360 + f*72 + rep*6 + k
__global__ void k_repA(float* __restrict__ out) {
    int id = blockIdx.x * blockDim.x + threadIdx.x;
    if (id >= NROW * NS) return;
    int s = id % NS;
    int row = id / NS;
    int r = row / 360;
    int rem = row - r * 360;
    int f = rem / 72;
    int k = (rem - f * 72) % NK;
    float2 v = g_V[((r * NF + f) * NK + k) * NS + s];
    out[(size_t)row * NS + s] = v.x;
    out[(size_t)(NROW + row) * NS + s] = v.y;
}

// ---------------- kernel 6: mic partials over s-chunks ----------------
// grid (NR, NF, MICCH), block 256: tid -> (kh in {0,1}, b in 0..127)
__global__ void k_micp(const float* __restrict__ T) {
    __shared__ float2 sV[NK][NS / MICCH];
    int r = blockIdx.x, f = blockIdx.y, c = blockIdx.z;
    int tid = threadIdx.x;
    const int CH = NS / MICCH;            // 100
    int s0 = c * CH;
    for (int i = tid; i < NK * CH; i += 256) {
        int k = i / CH, s = i - k * CH;
        sV[k][s] = g_V[((r * NF + f) * NK + k) * NS + s0 + s];
    }
    __syncthreads();

    int b  = tid & (NB - 1);
    int kh = tid >> 7;
    float mre[3] = {0.f, 0.f, 0.f}, mim[3] = {0.f, 0.f, 0.f};
    #pragma unroll 4
    for (int s = 0; s < CH; s++) {
        float t = __ldg(&T[(size_t)(s0 + s) * NB + b]);
        #pragma unroll
        for (int j = 0; j < 3; j++) {
            float2 v = sV[kh * 3 + j][s];
            mre[j] = fmaf(v.x, t, mre[j]);
            mim[j] = fmaf(v.y, t, mim[j]);
        }
    }
    int rfk = (r * NF + f) * NK + kh * 3;
    #pragma unroll
    for (int j = 0; j < 3; j++)
        g_micp[((size_t)c * NRFK + rfk + j) * NB + b] = make_float2(mre[j], mim[j]);
}

// ---------------- kernel 7: mic reduce + replicate ----------------
// id over NROW*NB
__global__ void k_micout(float* __restrict__ out) {
    int id = blockIdx.x * blockDim.x + threadIdx.x;
    if (id >= NROW * NB) return;
    int b = id & (NB - 1);
    int row = id >> 7;
    int r = row / 360;
    int rem = row - r * 360;
    int f = rem / 72;
    int k = (rem - f * 72) % NK;
    int rfk = (r * NF + f) * NK + k;
    float2 acc = make_float2(0.f, 0.f);
    #pragma unroll
    for (int c = 0; c < MICCH; c++) {
        float2 p = g_micp[((size_t)c * NRFK + rfk) * NB + b];
        acc.x += p.x; acc.y += p.y;
    }
    const size_t MICBASE = (size_t)2 * NROW * NS;
    out[MICBASE + (size_t)row * NB + b] = acc.x;
    out[MICBASE + (size_t)(NROW + row) * NB + b] = acc.y;
}

// ---------------- launcher ----------------
extern "C" void kernel_launch(void* const* d_in, const int* in_sizes, int n_in,
                              void* d_out, int out_size) {
    const float* T   = (const float*)d_in[0];  // [400,128]
    const float* w   = (const float*)d_in[1];  // [5,6,12]
    const float* th  = (const float*)d_in[2];  // [3600,1]
    const float* fv  = (const float*)d_in[3];  // [5]
    const float* txp = (const float*)d_in[4];  // [12,3]
    const float* rxp = (const float*)d_in[5];  // [16,3]
    const float* mp  = (const float*)d_in[6];  // [3600,3]
    const float* sp  = (const float*)d_in[7];  // [400,3]
    float* out = (float*)d_out;

    k_setup<<<(NF * NM + 255) / 256, 256>>>(w, th, fv, txp, rxp, mp);
    k_main<<<dim3(13, NF, NSPLIT / 8), 256>>>(sp, fv);
    k_reduce<<<(NF * NK * NS + NF * NR * NS + 255) / 256, 256>>>();
    k_V<<<(NR * NF * NK * NS + 255) / 256, 256>>>();
    k_repA<<<(NROW * NS + 255) / 256, 256>>>(out);
    k_micp<<<dim3(NR, NF, MICCH), 256>>>(T);
    k_micout<<<(NROW * NB + 255) / 256, 256>>>(out);
}